// round 1
// baseline (speedup 1.0000x reference)
#include <cuda_runtime.h>

// Problem constants
static constexpr int Tt = 4;
static constexpr int Bb = 16;
static constexpr int Cc = 512;
static constexpr int Nn = 1024;
static constexpr int Cr = 64;
static constexpr int TB = Tt * Bb;   // 64 rows after reshape

// Scratch (allocation-free: __device__ globals)
__device__ float g_buf[TB * Cc];     // GAP output  [64, 512]
__device__ float h1_buf[TB * Cr];    // fc1 out     [64, 64]
__device__ float h1n_buf[TB * Cr];   // bn1 out     [64, 64]
__device__ float h2_buf[TB * Cc];    // fc2 out     [64, 512]

// ---------------------------------------------------------------------------
// K1: LIF multistep (TAU=2, hard reset, v_th=1) + global average pool over N.
// One block per (b,c) pair; 256 threads; each thread owns 4 consecutive n via
// float4 loads. v carried in registers across the T=4 recurrence.
// g row index r = t*B + b, so g_buf index = t*B*C + (b*C + c) = t*8192 + bc.
// ---------------------------------------------------------------------------
__global__ void __launch_bounds__(256) lif_gap_kernel(const float* __restrict__ x) {
    const int bc  = blockIdx.x;        // b*C + c
    const int tid = threadIdx.x;       // 0..255

    float v0 = 0.f, v1 = 0.f, v2 = 0.f, v3 = 0.f;
    float tc[Tt];

    const float4* __restrict__ xp = reinterpret_cast<const float4*>(x);

    #pragma unroll
    for (int t = 0; t < Tt; t++) {
        // (( t*B + b )*C + c)*N/4 + tid  =  (t*B*C + bc)*256 + tid
        float4 xv = xp[(size_t)(t * Bb * Cc + bc) * 256 + tid];
        float cnt = 0.f;

        v0 = (v0 + xv.x) * 0.5f;
        { float s = (v0 >= 1.0f) ? 1.f : 0.f; cnt += s; v0 *= (1.f - s); }
        v1 = (v1 + xv.y) * 0.5f;
        { float s = (v1 >= 1.0f) ? 1.f : 0.f; cnt += s; v1 *= (1.f - s); }
        v2 = (v2 + xv.z) * 0.5f;
        { float s = (v2 >= 1.0f) ? 1.f : 0.f; cnt += s; v2 *= (1.f - s); }
        v3 = (v3 + xv.w) * 0.5f;
        { float s = (v3 >= 1.0f) ? 1.f : 0.f; cnt += s; v3 *= (1.f - s); }

        tc[t] = cnt;
    }

    // Block reduction of tc[0..3] over 256 threads.
    __shared__ float sdata[8][Tt];
    const int lane = tid & 31;
    const int warp = tid >> 5;

    #pragma unroll
    for (int t = 0; t < Tt; t++) {
        float val = tc[t];
        #pragma unroll
        for (int off = 16; off > 0; off >>= 1)
            val += __shfl_down_sync(0xffffffffu, val, off);
        if (lane == 0) sdata[warp][t] = val;
    }
    __syncthreads();

    if (tid < Tt) {
        float s = 0.f;
        #pragma unroll
        for (int w = 0; w < 8; w++) s += sdata[w][tid];
        g_buf[tid * Bb * Cc + bc] = s * (1.0f / (float)Nn);
    }
}

// ---------------------------------------------------------------------------
// K2: h1[r][j] = sum_c g[r][c] * w1[j][c] + b1[j]   (64x64, dot over 512)
// One block per row r (64 blocks), 64 threads (one per j).
// ---------------------------------------------------------------------------
__global__ void __launch_bounds__(Cr) mm1_kernel(const float* __restrict__ w1,
                                                 const float* __restrict__ b1) {
    __shared__ float gr[Cc];
    const int r = blockIdx.x;
    const int j = threadIdx.x;

    for (int i = j; i < Cc; i += Cr) gr[i] = g_buf[r * Cc + i];
    __syncthreads();

    const float* __restrict__ wr = w1 + (size_t)j * Cc;
    float a0 = 0.f, a1 = 0.f, a2 = 0.f, a3 = 0.f;
    #pragma unroll 4
    for (int i = 0; i < Cc; i += 4) {
        a0 += gr[i + 0] * wr[i + 0];
        a1 += gr[i + 1] * wr[i + 1];
        a2 += gr[i + 2] * wr[i + 2];
        a3 += gr[i + 3] * wr[i + 3];
    }
    h1_buf[r * Cr + j] = (a0 + a1) + (a2 + a3) + b1[j];
}

// ---------------------------------------------------------------------------
// K3: BN1 (training mode, biased var over the 64 rows) -> h1n
// 1 block, 64 threads; thread j owns column j.
// ---------------------------------------------------------------------------
__global__ void __launch_bounds__(Cr) bn1_kernel(const float* __restrict__ gamma1,
                                                 const float* __restrict__ beta1) {
    const int j = threadIdx.x;
    float s = 0.f, ss = 0.f;
    for (int r = 0; r < TB; r++) {
        float h = h1_buf[r * Cr + j];
        s += h; ss += h * h;
    }
    float mu  = s * (1.0f / TB);
    float var = ss * (1.0f / TB) - mu * mu;
    if (var < 0.f) var = 0.f;
    float sc = rsqrtf(var + 1e-5f) * gamma1[j];
    float sh = beta1[j];
    for (int r = 0; r < TB; r++)
        h1n_buf[r * Cr + j] = (h1_buf[r * Cr + j] - mu) * sc + sh;
}

// ---------------------------------------------------------------------------
// K4: h2[r][c] = sum_j h1n[r][j] * w2[c][j] + b2[c]   (64x512, dot over 64)
// One block per row r, 512 threads (one per c).
// ---------------------------------------------------------------------------
__global__ void __launch_bounds__(Cc) mm2_kernel(const float* __restrict__ w2,
                                                 const float* __restrict__ b2) {
    __shared__ float hr[Cr];
    const int r = blockIdx.x;
    const int c = threadIdx.x;

    if (c < Cr) hr[c] = h1n_buf[r * Cr + c];
    __syncthreads();

    const float* __restrict__ wr = w2 + (size_t)c * Cr;
    float acc = 0.f;
    #pragma unroll
    for (int j = 0; j < Cr; j++) acc += hr[j] * wr[j];
    h2_buf[r * Cc + c] = acc + b2[c];
}

// ---------------------------------------------------------------------------
// K5: BN2 + write output [T,B,C,1] row-major == [64, 512].
// 1 block, 512 threads; thread c owns column c.
// ---------------------------------------------------------------------------
__global__ void __launch_bounds__(Cc) bn2_kernel(const float* __restrict__ gamma2,
                                                 const float* __restrict__ beta2,
                                                 float* __restrict__ out) {
    const int c = threadIdx.x;
    float s = 0.f, ss = 0.f;
    for (int r = 0; r < TB; r++) {
        float h = h2_buf[r * Cc + c];
        s += h; ss += h * h;
    }
    float mu  = s * (1.0f / TB);
    float var = ss * (1.0f / TB) - mu * mu;
    if (var < 0.f) var = 0.f;
    float sc = rsqrtf(var + 1e-5f) * gamma2[c];
    float sh = beta2[c];
    for (int r = 0; r < TB; r++)
        out[r * Cc + c] = (h2_buf[r * Cc + c] - mu) * sc + sh;
}

// ---------------------------------------------------------------------------
extern "C" void kernel_launch(void* const* d_in, const int* in_sizes, int n_in,
                              void* d_out, int out_size) {
    const float* x      = (const float*)d_in[0];
    const float* w1     = (const float*)d_in[1];
    const float* b1     = (const float*)d_in[2];
    const float* gamma1 = (const float*)d_in[3];
    const float* beta1  = (const float*)d_in[4];
    const float* w2     = (const float*)d_in[5];
    const float* b2     = (const float*)d_in[6];
    const float* gamma2 = (const float*)d_in[7];
    const float* beta2  = (const float*)d_in[8];
    float* out = (float*)d_out;

    lif_gap_kernel<<<Bb * Cc, 256>>>(x);
    mm1_kernel<<<TB, Cr>>>(w1, b1);
    bn1_kernel<<<1, Cr>>>(gamma1, beta1);
    mm2_kernel<<<TB, Cc>>>(w2, b2);
    bn2_kernel<<<1, Cc>>>(gamma2, beta2, out);
}

// round 2
// speedup vs baseline: 1.9095x; 1.9095x over previous
#include <cuda_runtime.h>

// Problem constants
static constexpr int Tt = 4;
static constexpr int Bb = 16;
static constexpr int Cc = 512;
static constexpr int Nn = 1024;
static constexpr int Cr = 64;
static constexpr int TB = Tt * Bb;   // 64 rows after reshape

// Scratch (allocation-free: __device__ globals)
__device__ float g_buf[TB * Cc];     // GAP output  [64, 512]  (row-major [r][c])
__device__ float h1n_buf[TB * Cr];   // bn1 out     [64, 64]   (row-major [r][j])

// ---------------------------------------------------------------------------
// K1: LIF multistep (TAU=2, hard reset, v_th=1) + global average pool over N.
// One block per TWO (b,c) pairs; 256 threads; each thread owns one float4 per
// channel per t -> 8 independent front-batched LDG.128 per thread.
// ---------------------------------------------------------------------------
__global__ void __launch_bounds__(256) lif_gap_kernel(const float* __restrict__ x) {
    const int bc0 = blockIdx.x * 2;
    const int bc1 = bc0 + 1;
    const int tid = threadIdx.x;

    const float4* __restrict__ xp = reinterpret_cast<const float4*>(x);

    float4 xa[Tt], xb[Tt];
    #pragma unroll
    for (int t = 0; t < Tt; t++) {
        xa[t] = xp[(size_t)(t * Bb * Cc + bc0) * 256 + tid];
        xb[t] = xp[(size_t)(t * Bb * Cc + bc1) * 256 + tid];
    }

    float va0=0.f, va1=0.f, va2=0.f, va3=0.f;
    float vb0=0.f, vb1=0.f, vb2=0.f, vb3=0.f;
    float c8[8];

    #pragma unroll
    for (int t = 0; t < Tt; t++) {
        float ca = 0.f, cb = 0.f;
        va0 = (va0 + xa[t].x) * 0.5f; { float s = (va0 >= 1.f) ? 1.f : 0.f; ca += s; va0 *= (1.f - s); }
        va1 = (va1 + xa[t].y) * 0.5f; { float s = (va1 >= 1.f) ? 1.f : 0.f; ca += s; va1 *= (1.f - s); }
        va2 = (va2 + xa[t].z) * 0.5f; { float s = (va2 >= 1.f) ? 1.f : 0.f; ca += s; va2 *= (1.f - s); }
        va3 = (va3 + xa[t].w) * 0.5f; { float s = (va3 >= 1.f) ? 1.f : 0.f; ca += s; va3 *= (1.f - s); }
        vb0 = (vb0 + xb[t].x) * 0.5f; { float s = (vb0 >= 1.f) ? 1.f : 0.f; cb += s; vb0 *= (1.f - s); }
        vb1 = (vb1 + xb[t].y) * 0.5f; { float s = (vb1 >= 1.f) ? 1.f : 0.f; cb += s; vb1 *= (1.f - s); }
        vb2 = (vb2 + xb[t].z) * 0.5f; { float s = (vb2 >= 1.f) ? 1.f : 0.f; cb += s; vb2 *= (1.f - s); }
        vb3 = (vb3 + xb[t].w) * 0.5f; { float s = (vb3 >= 1.f) ? 1.f : 0.f; cb += s; vb3 *= (1.f - s); }
        c8[t]     = ca;
        c8[t + 4] = cb;
    }

    // Block reduction of 8 per-thread counters.
    __shared__ float sdata[8][8];   // [warp][val]
    const int lane = tid & 31;
    const int warp = tid >> 5;

    #pragma unroll
    for (int k = 0; k < 8; k++) {
        float val = c8[k];
        #pragma unroll
        for (int off = 16; off > 0; off >>= 1)
            val += __shfl_down_sync(0xffffffffu, val, off);
        if (lane == 0) sdata[warp][k] = val;
    }
    __syncthreads();

    if (tid < 8) {
        float s = 0.f;
        #pragma unroll
        for (int w = 0; w < 8; w++) s += sdata[w][tid];
        const int t  = tid & 3;
        const int bc = (tid < 4) ? bc0 : bc1;
        g_buf[t * Bb * Cc + bc] = s * (1.0f / (float)Nn);
    }
}

// ---------------------------------------------------------------------------
// T1: fused mm1 + bn1. One block per output column j (64 blocks, 256 threads).
//   h1[r] = dot(g[r,:], w1[j,:]) + b1[j]   (dot over 512, coalesced g reads)
//   column stats over 64 rows, write h1n[r][j].
// ---------------------------------------------------------------------------
__global__ void __launch_bounds__(256) t1_kernel(const float* __restrict__ w1,
                                                 const float* __restrict__ b1,
                                                 const float* __restrict__ gamma1,
                                                 const float* __restrict__ beta1) {
    __shared__ float ws[Cc];
    __shared__ float h1s[TB];
    __shared__ float stats[2];   // mu, sc

    const int j    = blockIdx.x;
    const int tid  = threadIdx.x;
    const int lane = tid & 31;
    const int warp = tid >> 5;

    // Stage w1 row j (coalesced).
    for (int i = tid; i < Cc; i += 256) ws[i] = w1[(size_t)j * Cc + i];
    __syncthreads();

    const float b1j = b1[j];

    // Each of 8 warps handles 8 rows; per row a 512-wide dot, coalesced.
    #pragma unroll
    for (int k = 0; k < 8; k++) {
        const int r = warp * 8 + k;
        const float* __restrict__ gr = g_buf + (size_t)r * Cc;
        float acc = 0.f;
        #pragma unroll
        for (int i = 0; i < 16; i++)
            acc += gr[i * 32 + lane] * ws[i * 32 + lane];
        #pragma unroll
        for (int off = 16; off > 0; off >>= 1)
            acc += __shfl_down_sync(0xffffffffu, acc, off);
        if (lane == 0) h1s[r] = acc + b1j;
    }
    __syncthreads();

    // Warp 0 computes column stats.
    if (warp == 0) {
        float a = h1s[lane], b = h1s[lane + 32];
        float s  = a + b;
        float ss = a * a + b * b;
        #pragma unroll
        for (int off = 16; off > 0; off >>= 1) {
            s  += __shfl_down_sync(0xffffffffu, s,  off);
            ss += __shfl_down_sync(0xffffffffu, ss, off);
        }
        if (lane == 0) {
            float mu  = s * (1.0f / TB);
            float var = ss * (1.0f / TB) - mu * mu;
            if (var < 0.f) var = 0.f;
            stats[0] = mu;
            stats[1] = rsqrtf(var + 1e-5f) * gamma1[j];
        }
    }
    __syncthreads();

    if (tid < TB) {
        h1n_buf[tid * Cr + j] = (h1s[tid] - stats[0]) * stats[1] + beta1[j];
    }
}

// ---------------------------------------------------------------------------
// T2: fused mm2 + bn2 + output write. One block per output column c
// (512 blocks, 64 threads; thread == row r).
// ---------------------------------------------------------------------------
__global__ void __launch_bounds__(64) t2_kernel(const float* __restrict__ w2,
                                                const float* __restrict__ b2,
                                                const float* __restrict__ gamma2,
                                                const float* __restrict__ beta2,
                                                float* __restrict__ out) {
    __shared__ float h1s[TB * (Cr + 1)];  // padded: [r][j] at r*65+j (no bank conflicts)
    __shared__ float w2s[Cr];
    __shared__ float wsum[2][2];          // per-warp partial (s, ss)

    const int c    = blockIdx.x;
    const int r    = threadIdx.x;         // 0..63
    const int lane = r & 31;
    const int warp = r >> 5;

    // Stage h1n [64x64] into padded shared (coalesced global reads).
    for (int i = r; i < TB * Cr; i += 64) {
        const int rr = i >> 6, jj = i & 63;
        h1s[rr * (Cr + 1) + jj] = h1n_buf[i];
    }
    w2s[r] = w2[(size_t)c * Cr + r];
    __syncthreads();

    float acc = 0.f;
    const float* __restrict__ hr = h1s + r * (Cr + 1);
    #pragma unroll
    for (int j = 0; j < Cr; j++) acc += hr[j] * w2s[j];
    const float h = acc + b2[c];

    // Block stats over 64 rows (2 warps).
    float s = h, ss = h * h;
    #pragma unroll
    for (int off = 16; off > 0; off >>= 1) {
        s  += __shfl_down_sync(0xffffffffu, s,  off);
        ss += __shfl_down_sync(0xffffffffu, ss, off);
    }
    if (lane == 0) { wsum[warp][0] = s; wsum[warp][1] = ss; }
    __syncthreads();

    const float S  = wsum[0][0] + wsum[1][0];
    const float SS = wsum[0][1] + wsum[1][1];
    const float mu  = S * (1.0f / TB);
    float var = SS * (1.0f / TB) - mu * mu;
    if (var < 0.f) var = 0.f;
    const float sc = rsqrtf(var + 1e-5f) * gamma2[c];

    out[r * Cc + c] = (h - mu) * sc + beta2[c];
}

// ---------------------------------------------------------------------------
extern "C" void kernel_launch(void* const* d_in, const int* in_sizes, int n_in,
                              void* d_out, int out_size) {
    const float* x      = (const float*)d_in[0];
    const float* w1     = (const float*)d_in[1];
    const float* b1     = (const float*)d_in[2];
    const float* gamma1 = (const float*)d_in[3];
    const float* beta1  = (const float*)d_in[4];
    const float* w2     = (const float*)d_in[5];
    const float* b2     = (const float*)d_in[6];
    const float* gamma2 = (const float*)d_in[7];
    const float* beta2  = (const float*)d_in[8];
    float* out = (float*)d_out;

    lif_gap_kernel<<<(Bb * Cc) / 2, 256>>>(x);
    t1_kernel<<<Cr, 256>>>(w1, b1, gamma1, beta1);
    t2_kernel<<<Cc, 64>>>(w2, b2, gamma2, beta2, out);
}

// round 3
// speedup vs baseline: 2.1857x; 1.1446x over previous
#include <cuda_runtime.h>

// Problem constants
static constexpr int Tt = 4;
static constexpr int Bb = 16;
static constexpr int Cc = 512;
static constexpr int Nn = 1024;
static constexpr int Cr = 64;
static constexpr int TB = Tt * Bb;     // 64 rows
static constexpr int BC = Bb * Cc;     // 8192 channels

// Scratch + barrier state (zero-initialized at module load; counters are
// monotonic across graph replays — no reset needed, see barrier derivation).
__device__ float g_buf[TB * Cc];       // GAP output [64, 512] row-major
__device__ float h1n_buf[TB * Cr];     // bn1 output [64, 64] row-major
__device__ unsigned g_arrive;
__device__ volatile unsigned g_release;

// LIF step: v += x; v/=2 (tau=2); spike if v>=1 -> count, hard reset.
#define LIF_STEP(v, xval, pk, inc) \
    do { v = (v + (xval)) * 0.5f; if (v >= 1.0f) { pk += (inc); v = 0.0f; } } while (0)

__global__ void __launch_bounds__(256, 4)
fused_kernel(const float* __restrict__ x,
             const float* __restrict__ w1, const float* __restrict__ b1,
             const float* __restrict__ gamma1, const float* __restrict__ beta1,
             const float* __restrict__ w2, const float* __restrict__ b2,
             const float* __restrict__ gamma2, const float* __restrict__ beta2,
             float* __restrict__ out, int nb)
{
    __shared__ float sh[4240];   // phase-union: C needs 64*65 + 64 + 4 = 4228
    const int tid  = threadIdx.x;
    const int lane = tid & 31;
    const int warp = tid >> 5;

    // ---------------- grid-wide barrier ----------------
    // Arrival counter is monotonic across launches (nb*2 increments per
    // launch, so it is always a multiple of nb at launch start). Barrier
    // sequence number B = ceil(v/nb) is identical for all nb arrivals of one
    // barrier; the v%nb==0 arrival publishes g_release=B. No per-launch base.
    auto grid_sync = [&]() {
        __threadfence();
        __syncthreads();
        if (tid == 0) {
            unsigned v = atomicAdd(&g_arrive, 1u) + 1u;
            unsigned B = (v + (unsigned)nb - 1u) / (unsigned)nb;
            if (v == B * (unsigned)nb) g_release = B;
            while (g_release < B) { __nanosleep(32); }
            __threadfence();
        }
        __syncthreads();
    };

    // =====================================================================
    // Phase A: LIF multistep + GAP. One warp per channel PAIR, no smem/sync.
    // Each warp-task: 2 channels x 8 chunks x (4 t-steps of float4) loads.
    // Spike counts packed as 16-bit fields (max 32/lane, 1024/warp) and
    // reduced with REDUX.
    // =====================================================================
    {
        const float4* __restrict__ xp = reinterpret_cast<const float4*>(x);
        const int G  = nb * 8;                     // total warps
        const int gw = blockIdx.x * 8 + warp;

        for (int task = gw; task < BC / 2; task += G) {
            const int bc0 = task * 2;
            const int bc1 = bc0 + 1;
            unsigned pa01 = 0, pa23 = 0, pb01 = 0, pb23 = 0;

            float va0=0.f, va1=0.f, va2=0.f, va3=0.f;
            float vb0=0.f, vb1=0.f, vb2=0.f, vb3=0.f;

            #pragma unroll 2
            for (int ch = 0; ch < 8; ch++) {
                const int off = ch * 32 + lane;
                // 8 independent LDG.128 front-batched
                float4 xa0 = xp[(size_t)(0 * BC + bc0) * 256 + off];
                float4 xa1 = xp[(size_t)(1 * BC + bc0) * 256 + off];
                float4 xa2 = xp[(size_t)(2 * BC + bc0) * 256 + off];
                float4 xa3 = xp[(size_t)(3 * BC + bc0) * 256 + off];
                float4 xb0 = xp[(size_t)(0 * BC + bc1) * 256 + off];
                float4 xb1 = xp[(size_t)(1 * BC + bc1) * 256 + off];
                float4 xb2 = xp[(size_t)(2 * BC + bc1) * 256 + off];
                float4 xb3 = xp[(size_t)(3 * BC + bc1) * 256 + off];

                va0=0.f; va1=0.f; va2=0.f; va3=0.f;
                vb0=0.f; vb1=0.f; vb2=0.f; vb3=0.f;

                // t = 0 -> pa01 low half
                LIF_STEP(va0, xa0.x, pa01, 1u); LIF_STEP(va1, xa0.y, pa01, 1u);
                LIF_STEP(va2, xa0.z, pa01, 1u); LIF_STEP(va3, xa0.w, pa01, 1u);
                LIF_STEP(vb0, xb0.x, pb01, 1u); LIF_STEP(vb1, xb0.y, pb01, 1u);
                LIF_STEP(vb2, xb0.z, pb01, 1u); LIF_STEP(vb3, xb0.w, pb01, 1u);
                // t = 1 -> pa01 high half
                LIF_STEP(va0, xa1.x, pa01, 65536u); LIF_STEP(va1, xa1.y, pa01, 65536u);
                LIF_STEP(va2, xa1.z, pa01, 65536u); LIF_STEP(va3, xa1.w, pa01, 65536u);
                LIF_STEP(vb0, xb1.x, pb01, 65536u); LIF_STEP(vb1, xb1.y, pb01, 65536u);
                LIF_STEP(vb2, xb1.z, pb01, 65536u); LIF_STEP(vb3, xb1.w, pb01, 65536u);
                // t = 2 -> pa23 low half
                LIF_STEP(va0, xa2.x, pa23, 1u); LIF_STEP(va1, xa2.y, pa23, 1u);
                LIF_STEP(va2, xa2.z, pa23, 1u); LIF_STEP(va3, xa2.w, pa23, 1u);
                LIF_STEP(vb0, xb2.x, pb23, 1u); LIF_STEP(vb1, xb2.y, pb23, 1u);
                LIF_STEP(vb2, xb2.z, pb23, 1u); LIF_STEP(vb3, xb2.w, pb23, 1u);
                // t = 3 -> pa23 high half
                LIF_STEP(va0, xa3.x, pa23, 65536u); LIF_STEP(va1, xa3.y, pa23, 65536u);
                LIF_STEP(va2, xa3.z, pa23, 65536u); LIF_STEP(va3, xa3.w, pa23, 65536u);
                LIF_STEP(vb0, xb3.x, pb23, 65536u); LIF_STEP(vb1, xb3.y, pb23, 65536u);
                LIF_STEP(vb2, xb3.z, pb23, 65536u); LIF_STEP(vb3, xb3.w, pb23, 65536u);
            }

            pa01 = __reduce_add_sync(0xffffffffu, pa01);
            pa23 = __reduce_add_sync(0xffffffffu, pa23);
            pb01 = __reduce_add_sync(0xffffffffu, pb01);
            pb23 = __reduce_add_sync(0xffffffffu, pb23);

            if (lane < 8) {
                const int t  = lane & 3;
                const int bc = (lane < 4) ? bc0 : bc1;
                const unsigned p01 = (lane < 4) ? pa01 : pb01;
                const unsigned p23 = (lane < 4) ? pa23 : pb23;
                const unsigned cnt = (t < 2) ? ((p01 >> (16 * t)) & 0xFFFFu)
                                             : ((p23 >> (16 * (t - 2))) & 0xFFFFu);
                g_buf[t * BC + bc] = (float)cnt * (1.0f / (float)Nn);
            }
        }
    }

    grid_sync();

    // =====================================================================
    // Phase B: mm1 + bn1. Block j handles output column j (grid-stride).
    // =====================================================================
    {
        float* ws    = sh;        // [512]
        float* h1s   = sh + 512;  // [64]
        float* stats = sh + 576;  // [2]

        for (int j = blockIdx.x; j < Cr; j += nb) {
            for (int i = tid; i < Cc; i += 256) ws[i] = w1[(size_t)j * Cc + i];
            __syncthreads();

            const float b1j = b1[j];
            #pragma unroll
            for (int k = 0; k < 8; k++) {
                const int r = warp * 8 + k;
                const float* __restrict__ gr = g_buf + (size_t)r * Cc;
                float acc = 0.f;
                #pragma unroll
                for (int i = 0; i < 16; i++)
                    acc += gr[i * 32 + lane] * ws[i * 32 + lane];
                #pragma unroll
                for (int off = 16; off > 0; off >>= 1)
                    acc += __shfl_down_sync(0xffffffffu, acc, off);
                if (lane == 0) h1s[r] = acc + b1j;
            }
            __syncthreads();

            if (warp == 0) {
                float a = h1s[lane], b = h1s[lane + 32];
                float s  = a + b;
                float ss = a * a + b * b;
                #pragma unroll
                for (int off = 16; off > 0; off >>= 1) {
                    s  += __shfl_down_sync(0xffffffffu, s,  off);
                    ss += __shfl_down_sync(0xffffffffu, ss, off);
                }
                if (lane == 0) {
                    float mu  = s * (1.0f / TB);
                    float var = ss * (1.0f / TB) - mu * mu;
                    if (var < 0.f) var = 0.f;
                    stats[0] = mu;
                    stats[1] = rsqrtf(var + 1e-5f) * gamma1[j];
                }
            }
            __syncthreads();

            if (tid < TB)
                h1n_buf[tid * Cr + j] = (h1s[tid] - stats[0]) * stats[1] + beta1[j];
            __syncthreads();   // protect smem before next grid-stride iter
        }
    }

    grid_sync();

    // =====================================================================
    // Phase C: mm2 + bn2 + output. Block c handles output column c.
    // h1n staged once (float4, all 256 threads) into padded smem.
    // =====================================================================
    {
        float* h1s  = sh;          // [64 * 65] padded
        float* w2s  = sh + 4160;   // [64]
        float* wsum = sh + 4224;   // [4]

        {
            const float4* __restrict__ hp = reinterpret_cast<const float4*>(h1n_buf);
            for (int i4 = tid; i4 < (TB * Cr) / 4; i4 += 256) {
                float4 v = hp[i4];
                const int i  = i4 * 4;
                const int rr = i >> 6, jj = i & 63;
                float* d = &h1s[rr * 65 + jj];
                d[0] = v.x; d[1] = v.y; d[2] = v.z; d[3] = v.w;
            }
        }
        __syncthreads();

        for (int c = blockIdx.x; c < Cc; c += nb) {
            if (tid < Cr) w2s[tid] = w2[(size_t)c * Cr + tid];
            __syncthreads();

            float h = 0.f;
            if (tid < TB) {
                const float* __restrict__ hr = h1s + tid * 65;
                float acc = 0.f;
                #pragma unroll
                for (int j = 0; j < Cr; j++) acc += hr[j] * w2s[j];
                h = acc + b2[c];

                float s = h, ss = h * h;
                #pragma unroll
                for (int off = 16; off > 0; off >>= 1) {
                    s  += __shfl_down_sync(0xffffffffu, s,  off);
                    ss += __shfl_down_sync(0xffffffffu, ss, off);
                }
                if (lane == 0) { wsum[warp * 2] = s; wsum[warp * 2 + 1] = ss; }
            }
            __syncthreads();

            if (tid < TB) {
                const float S  = wsum[0] + wsum[2];
                const float SS = wsum[1] + wsum[3];
                const float mu = S * (1.0f / TB);
                float var = SS * (1.0f / TB) - mu * mu;
                if (var < 0.f) var = 0.f;
                const float sc = rsqrtf(var + 1e-5f) * gamma2[c];
                out[tid * Cc + c] = (h - mu) * sc + beta2[c];
            }
            __syncthreads();   // protect w2s/wsum before next iter
        }
    }
}

// ---------------------------------------------------------------------------
extern "C" void kernel_launch(void* const* d_in, const int* in_sizes, int n_in,
                              void* d_out, int out_size) {
    const float* x      = (const float*)d_in[0];
    const float* w1     = (const float*)d_in[1];
    const float* b1     = (const float*)d_in[2];
    const float* gamma1 = (const float*)d_in[3];
    const float* beta1  = (const float*)d_in[4];
    const float* w2     = (const float*)d_in[5];
    const float* b2     = (const float*)d_in[6];
    const float* gamma2 = (const float*)d_in[7];
    const float* beta2  = (const float*)d_in[8];
    float* out = (float*)d_out;

    int dev = 0;
    cudaGetDevice(&dev);
    int sms = 0;
    cudaDeviceGetAttribute(&sms, cudaDevAttrMultiProcessorCount, dev);
    int maxb = 0;
    cudaOccupancyMaxActiveBlocksPerMultiprocessor(&maxb, fused_kernel, 256, 0);
    if (maxb < 1) maxb = 1;
    if (sms < 1) sms = 1;
    int nb = sms * maxb;
    if (nb > 592) nb = 592;   // 4096 phase-A warp-tasks; more blocks add no work

    fused_kernel<<<nb, 256>>>(x, w1, b1, gamma1, beta1,
                              w2, b2, gamma2, beta2, out, nb);
}